// round 3
// baseline (speedup 1.0000x reference)
#include <cuda_runtime.h>

#define TB        32
#define NTHREADS  256
#define OBS       464
#define SROW      260      // padded activation row stride (floats): kills A-load bank conflicts

typedef unsigned long long ull;

// ---------- f32x2 helpers ----------
__device__ __forceinline__ ull pk2(float lo, float hi) {
    ull r; asm("mov.b64 %0, {%1, %2};" : "=l"(r) : "f"(lo), "f"(hi)); return r;
}
__device__ __forceinline__ float2 upk2(ull v) {
    float2 f; asm("mov.b64 {%0, %1}, %2;" : "=f"(f.x), "=f"(f.y) : "l"(v)); return f;
}
__device__ __forceinline__ void fma2(ull& d, ull a, ull b) {
    asm("fma.rn.f32x2 %0, %1, %2, %0;" : "+l"(d) : "l"(a), "l"(b));
}

// tanh(x) = 1 - 2/(exp(2x)+1): ~1e-6 rel err (ex2 + rcp on MUFU pipe)
__device__ __forceinline__ float ftanh(float x) {
    float e = __expf(x + x);
    return 1.0f - __fdividef(2.0f, e + 1.0f);
}

// ---------- cp.async ----------
__device__ __forceinline__ void cpa16(void* s, const void* g) {
    unsigned sa = (unsigned)__cvta_generic_to_shared(s);
    asm volatile("cp.async.cg.shared.global [%0], [%1], 16;" :: "r"(sa), "l"(g));
}
#define CPCOMMIT() asm volatile("cp.async.commit_group;")
#define CPWAIT1()  asm volatile("cp.async.wait_group 1;")

// prefetch one 16x256 half-chunk (4096 floats) of W into smem
__device__ __forceinline__ void pf_half(float* dst, const float* src, int tid) {
#pragma unroll
    for (int i = 0; i < 4; ++i)
        cpa16(dst + (i * 256 + tid) * 4, src + (i * 256 + tid) * 4);
}

// ---------- acc helpers: 4 rows x 4 f32x2 pairs (8 cols) ----------
__device__ __forceinline__ void acc_zero(ull acc[4][4]) {
#pragma unroll
    for (int r = 0; r < 4; ++r)
#pragma unroll
        for (int p = 0; p < 4; ++p) acc[r][p] = 0ULL;
}
__device__ __forceinline__ void acc_bias(ull acc[4][4], const float* __restrict__ b, int gcol) {
    float4 b0 = *reinterpret_cast<const float4*>(b + gcol);
    float4 b1 = *reinterpret_cast<const float4*>(b + gcol + 4);
    ull p0 = pk2(b0.x, b0.y), p1 = pk2(b0.z, b0.w);
    ull p2 = pk2(b1.x, b1.y), p3 = pk2(b1.z, b1.w);
#pragma unroll
    for (int r = 0; r < 4; ++r) {
        acc[r][0] = p0; acc[r][1] = p1; acc[r][2] = p2; acc[r][3] = p3;
    }
}
__device__ __forceinline__ void epi_raw(float* dst, int dstride, int grow0, int gcol,
                                        const ull acc[4][4]) {
#pragma unroll
    for (int r = 0; r < 4; ++r) {
        float* p = dst + (grow0 + r) * dstride + gcol;
        float2 t0 = upk2(acc[r][0]), t1 = upk2(acc[r][1]);
        float2 t2 = upk2(acc[r][2]), t3 = upk2(acc[r][3]);
        *reinterpret_cast<float4*>(p)     = make_float4(t0.x, t0.y, t1.x, t1.y);
        *reinterpret_cast<float4*>(p + 4) = make_float4(t2.x, t2.y, t3.x, t3.y);
    }
}
__device__ __forceinline__ void epi_tanh(float* dst, int dstride, int grow0, int gcol,
                                         const ull acc[4][4]) {
#pragma unroll
    for (int r = 0; r < 4; ++r) {
        float* p = dst + (grow0 + r) * dstride + gcol;
        float2 t0 = upk2(acc[r][0]), t1 = upk2(acc[r][1]);
        float2 t2 = upk2(acc[r][2]), t3 = upk2(acc[r][3]);
        *reinterpret_cast<float4*>(p) =
            make_float4(ftanh(t0.x), ftanh(t0.y), ftanh(t1.x), ftanh(t1.y));
        *reinterpret_cast<float4*>(p + 4) =
            make_float4(ftanh(t2.x), ftanh(t2.y), ftanh(t3.x), ftanh(t3.y));
    }
}

// ---------- GEMM: [32 x 256] += A[32 x 16*nhalf] * W[16*nhalf x 256] ----------
// Warp tile: 16 rows x 64 cols; thread tile 4x8 (rows grow0..+3, cols gcol..+7).
// W streamed via cp.async double-buffered 16-row half-chunks.
__device__ __forceinline__ void gemm_tiles(
    ull acc[4][4], const float* __restrict__ sA, int astride, int grow0, int gcol,
    const float* __restrict__ W, int nhalf, float* __restrict__ sW, int tid)
{
    pf_half(sW, W, tid);
    CPCOMMIT();
    for (int c = 0; c < nhalf; ++c) {
        __syncthreads();                    // all warps done with buf (c+1)&1 (chunk c-1)
        if (c + 1 < nhalf) pf_half(sW + ((c + 1) & 1) * 4096, W + (c + 1) * 4096, tid);
        CPCOMMIT();                         // always commit (maybe empty) so WAIT1 => chunk c done
        CPWAIT1();
        __syncthreads();                    // chunk c visible to all
        const float* buf = sW + (c & 1) * 4096;
        const float* Ab = sA + grow0 * astride + c * 16;
#pragma unroll
        for (int k4 = 0; k4 < 16; k4 += 4) {
            float a[4][4];
#pragma unroll
            for (int r = 0; r < 4; ++r)
                *reinterpret_cast<float4*>(a[r]) =
                    *reinterpret_cast<const float4*>(Ab + r * astride + k4);
#pragma unroll
            for (int kk = 0; kk < 4; ++kk) {
                const ulonglong2* wr =
                    reinterpret_cast<const ulonglong2*>(buf + (k4 + kk) * 256 + gcol);
                ulonglong2 w01 = wr[0], w23 = wr[1];
#pragma unroll
                for (int r = 0; r < 4; ++r) {
                    ull a2 = pk2(a[r][kk], a[r][kk]);
                    fma2(acc[r][0], a2, w01.x);
                    fma2(acc[r][1], a2, w01.y);
                    fma2(acc[r][2], a2, w23.x);
                    fma2(acc[r][3], a2, w23.y);
                }
            }
        }
    }
}

// ---------- attention with online softmax (emb computed once per entity) ----------
// Warp-private: warp owns the row; lane owns cols c0..c0+3 and c1..c1+3.
template<int N, int F>
__device__ __forceinline__ void attend_group(
    const float* __restrict__ feats,           // smem: N*F features of this row
    const float* __restrict__ Wg,              // smem: F x 256
    const float* __restrict__ bg,              // smem: 256
    float* __restrict__ qv,                    // smem: q in, vi out (256-float slot)
    int c0, int c1)
{
    float4 q0 = *reinterpret_cast<const float4*>(qv + c0);
    float4 q1 = *reinterpret_cast<const float4*>(qv + c1);
    ulonglong2 bb01 = *reinterpret_cast<const ulonglong2*>(bg + c0);
    ulonglong2 bb23 = *reinterpret_cast<const ulonglong2*>(bg + c1);

    float m = -3.0e38f, s = 0.0f;
    float v[8];
#pragma unroll
    for (int i = 0; i < 8; ++i) v[i] = 0.0f;

#pragma unroll 1
    for (int n = 0; n < N; ++n) {
        const float* fp = feats + n * F;
        ull a0 = bb01.x, a1 = bb01.y, a2 = bb23.x, a3 = bb23.y;
#pragma unroll
        for (int j = 0; j < F; ++j) {
            float fv = fp[j];
            ull f2 = pk2(fv, fv);
            ulonglong2 w01 = *reinterpret_cast<const ulonglong2*>(Wg + j * 256 + c0);
            ulonglong2 w23 = *reinterpret_cast<const ulonglong2*>(Wg + j * 256 + c1);
            fma2(a0, f2, w01.x); fma2(a1, f2, w01.y);
            fma2(a2, f2, w23.x); fma2(a3, f2, w23.y);
        }
        float e[8];
        float2 t;
        t = upk2(a0); e[0] = ftanh(t.x); e[1] = ftanh(t.y);
        t = upk2(a1); e[2] = ftanh(t.x); e[3] = ftanh(t.y);
        t = upk2(a2); e[4] = ftanh(t.x); e[5] = ftanh(t.y);
        t = upk2(a3); e[6] = ftanh(t.x); e[7] = ftanh(t.y);

        float beta = q0.x * e[0] + q0.y * e[1] + q0.z * e[2] + q0.w * e[3]
                   + q1.x * e[4] + q1.y * e[5] + q1.z * e[6] + q1.w * e[7];
#pragma unroll
        for (int sh = 16; sh > 0; sh >>= 1) beta += __shfl_xor_sync(0xffffffffu, beta, sh);

        float mn = fmaxf(m, beta);
        float scale = __expf(m - mn);      // 0 on first iter (m = -3e38)
        float wgt   = __expf(beta - mn);
        s = s * scale + wgt;
#pragma unroll
        for (int i = 0; i < 8; ++i) v[i] = v[i] * scale + wgt * e[i];
        m = mn;
    }
    float inv = __fdividef(1.0f, s);
    *reinterpret_cast<float4*>(qv + c0) =
        make_float4(v[0] * inv, v[1] * inv, v[2] * inv, v[3] * inv);
    *reinterpret_cast<float4*>(qv + c1) =
        make_float4(v[4] * inv, v[5] * inv, v[6] * inv, v[7] * inv);
}

// Shared memory layout (floats):
//  sIn  @ 0     : 32*464 = 14848  (inputs; reused as h, stride 260, after attention)
//  sEmb @ 14848 : 32*260 =  8320  (emb_self -> gi)
//  sQ   @ 23168 : 3*8320 = 24960  (q_other|q_box|q_ramp -> vi_*)
//  sW   @ 48128 : 9728            (GEMM double buffer 2x4096 / entity weights+biases)
// total 57856 floats = 231424 bytes
#define SMEM_FLOATS 57856
#define SMEM_BYTES  (SMEM_FLOATS * 4)

__global__ void __launch_bounds__(NTHREADS, 1)
obs_encoder_kernel(
    const float* __restrict__ gIn,
    const float* __restrict__ W_self,  const float* __restrict__ b_self,
    const float* __restrict__ W_other, const float* __restrict__ b_other,
    const float* __restrict__ W_box,   const float* __restrict__ b_box,
    const float* __restrict__ W_ramp,  const float* __restrict__ b_ramp,
    const float* __restrict__ corr_other, const float* __restrict__ corr_box,
    const float* __restrict__ corr_ramp,
    const float* __restrict__ W_fc, const float* __restrict__ b_fc,
    const float* __restrict__ W_e1, const float* __restrict__ b_e1,
    const float* __restrict__ W_e2, const float* __restrict__ b_e2,
    float* __restrict__ out)
{
    extern __shared__ float sm[];
    float* sIn  = sm;
    float* sEmb = sm + 14848;
    float* sQ   = sm + 23168;
    float* sW   = sm + 48128;

    const int tid  = threadIdx.x;
    const int lane = tid & 31;
    const int w    = tid >> 5;
    // GEMM mapping: warp tile 16 rows x 64 cols
    const int lr = lane >> 3, lc = lane & 7;
    const int grow0 = (w & 1) * 16 + lr * 4;          // 4 consecutive block-local rows
    const int gcol  = (w >> 1) * 64 + lc * 8;         // 8 consecutive cols
    // attention mapping: warp owns rows w*4..w*4+3; lane owns cols c0,c1
    const int c0 = lane * 4, c1 = c0 + 128;
    const size_t row0 = (size_t)blockIdx.x * TB;

    // ---- phase 0: stage 32 input rows ----
    {
        const float2* src = reinterpret_cast<const float2*>(gIn + row0 * OBS);
        float2* dst = reinterpret_cast<float2*>(sIn);
#pragma unroll
        for (int i = 0; i < 29; ++i) dst[i * 256 + tid] = src[i * 256 + tid];
    }
    __syncthreads();

    // ---- phase 1: emb_self = tanh(self_in @ W_self + b_self), K=10 ----
    {
        ull acc[4][4];
        acc_bias(acc, b_self, gcol);
#pragma unroll
        for (int k = 0; k < 10; ++k) {
            const ulonglong2* wr =
                reinterpret_cast<const ulonglong2*>(W_self + k * 256 + gcol);
            ulonglong2 w01 = wr[0], w23 = wr[1];
#pragma unroll
            for (int r = 0; r < 4; ++r) {
                float a = sIn[(grow0 + r) * OBS + k];
                ull a2 = pk2(a, a);
                fma2(acc[r][0], a2, w01.x); fma2(acc[r][1], a2, w01.y);
                fma2(acc[r][2], a2, w23.x); fma2(acc[r][3], a2, w23.y);
            }
        }
        epi_tanh(sEmb, SROW, grow0, gcol, acc);
    }
    // gemm_tiles' internal syncs order the sEmb stores before first compute

    // ---- phase 2: q_g = emb_self @ corr_g, gi = tanh(emb_self @ W_fc + b_fc) ----
    {
        ull acc[4][4];
        acc_zero(acc);
        gemm_tiles(acc, sEmb, SROW, grow0, gcol, corr_other, 16, sW, tid);
        epi_raw(sQ, SROW, grow0, gcol, acc);

        acc_zero(acc);
        gemm_tiles(acc, sEmb, SROW, grow0, gcol, corr_box, 16, sW, tid);
        epi_raw(sQ + 8320, SROW, grow0, gcol, acc);

        acc_zero(acc);
        gemm_tiles(acc, sEmb, SROW, grow0, gcol, corr_ramp, 16, sW, tid);
        epi_raw(sQ + 16640, SROW, grow0, gcol, acc);

        acc_bias(acc, b_fc, gcol);
        gemm_tiles(acc, sEmb, SROW, grow0, gcol, W_fc, 16, sW, tid);
        __syncthreads();   // all A-reads of emb_self done before overwrite with gi
        epi_tanh(sEmb, SROW, grow0, gcol, acc);
    }

    // ---- phase 3: attention pools (warp-private rows, online softmax) ----
    {
        __syncthreads();   // gi stores + last gemm done before sW overwrite
        // stage entity weights + biases into sW
        for (int i = tid; i < 2560; i += NTHREADS) sW[i]        = W_other[i];
        sW[2560 + tid] = b_other[tid];
        for (int i = tid; i < 3328; i += NTHREADS) sW[2816 + i] = W_box[i];
        sW[6144 + tid] = b_box[tid];
        for (int i = tid; i < 3072; i += NTHREADS) sW[6400 + i] = W_ramp[i];
        sW[9472 + tid] = b_ramp[tid];
        __syncthreads();

#pragma unroll 1
        for (int r = 0; r < 4; ++r) {
            const int row = w * 4 + r;
            const float* inrow = sIn + row * OBS;
            attend_group<15, 10>(inrow + 10,  sW,        sW + 2560, sQ + row * SROW,         c0, c1);
            attend_group<16, 13>(inrow + 160, sW + 2816, sW + 6144, sQ + 8320 + row * SROW,  c0, c1);
            attend_group<8, 12>( inrow + 368, sW + 6400, sW + 9472, sQ + 16640 + row * SROW, c0, c1);
        }
        __syncthreads();   // attention done before sW reuse + vi reads by other warps
    }

    // ---- phase 4: h = tanh(cat @ W_e1 + b_e1), cat = [gi | vi_o | vi_b | vi_r] ----
    {
        ull acc[4][4];
        acc_bias(acc, b_e1, gcol);
        gemm_tiles(acc, sEmb,       SROW, grow0, gcol, W_e1,          16, sW, tid);
        gemm_tiles(acc, sQ,         SROW, grow0, gcol, W_e1 + 65536,  16, sW, tid);
        gemm_tiles(acc, sQ + 8320,  SROW, grow0, gcol, W_e1 + 131072, 16, sW, tid);
        gemm_tiles(acc, sQ + 16640, SROW, grow0, gcol, W_e1 + 196608, 16, sW, tid);
        // sIn (inputs) is dead now; reuse as h (stride 260). Other warps only read
        // sEmb/sQ as A during phase 4, so no extra sync needed before this store.
        epi_tanh(sIn, SROW, grow0, gcol, acc);
    }

    // ---- phase 5: out = tanh(h @ W_e2 + b_e2) ----
    {
        ull acc[4][4];
        acc_bias(acc, b_e2, gcol);
        gemm_tiles(acc, sIn, SROW, grow0, gcol, W_e2, 16, sW, tid);  // internal sync orders h
#pragma unroll
        for (int r = 0; r < 4; ++r) {
            float* p = out + (row0 + grow0 + r) * 256 + gcol;
            float2 t0 = upk2(acc[r][0]), t1 = upk2(acc[r][1]);
            float2 t2 = upk2(acc[r][2]), t3 = upk2(acc[r][3]);
            *reinterpret_cast<float4*>(p) =
                make_float4(ftanh(t0.x), ftanh(t0.y), ftanh(t1.x), ftanh(t1.y));
            *reinterpret_cast<float4*>(p + 4) =
                make_float4(ftanh(t2.x), ftanh(t2.y), ftanh(t3.x), ftanh(t3.y));
        }
    }
}

extern "C" void kernel_launch(void* const* d_in, const int* in_sizes, int n_in,
                              void* d_out, int out_size) {
    const float* inputs     = (const float*)d_in[0];
    const float* W_self     = (const float*)d_in[1];
    const float* b_self     = (const float*)d_in[2];
    const float* W_other    = (const float*)d_in[3];
    const float* b_other    = (const float*)d_in[4];
    const float* W_box      = (const float*)d_in[5];
    const float* b_box      = (const float*)d_in[6];
    const float* W_ramp     = (const float*)d_in[7];
    const float* b_ramp     = (const float*)d_in[8];
    const float* corr_other = (const float*)d_in[9];
    const float* corr_box   = (const float*)d_in[10];
    const float* corr_ramp  = (const float*)d_in[11];
    const float* W_fc       = (const float*)d_in[12];
    const float* b_fc       = (const float*)d_in[13];
    const float* W_e1       = (const float*)d_in[14];
    const float* b_e1       = (const float*)d_in[15];
    const float* W_e2       = (const float*)d_in[16];
    const float* b_e2       = (const float*)d_in[17];
    float* out = (float*)d_out;

    const int B = in_sizes[0] / OBS;       // 32768
    const int nblocks = B / TB;            // 1024

    cudaFuncSetAttribute(obs_encoder_kernel,
                         cudaFuncAttributeMaxDynamicSharedMemorySize, SMEM_BYTES);

    obs_encoder_kernel<<<nblocks, NTHREADS, SMEM_BYTES>>>(
        inputs, W_self, b_self, W_other, b_other, W_box, b_box, W_ramp, b_ramp,
        corr_other, corr_box, corr_ramp, W_fc, b_fc, W_e1, b_e1, W_e2, b_e2, out);
}